// round 2
// baseline (speedup 1.0000x reference)
#include <cuda_runtime.h>
#include <math.h>

// Problem constants (guarded at runtime against in_sizes)
#define NMAX 100000
#define EMAX 1700000
#define HID  64
#define NCLS 40
#define GRED 256        // column-reduction grid
#define SCAN_B 1024

// -------- scratch (device globals: no allocations allowed) --------
__device__ int   g_rowptr[NMAX + 1];
__device__ int   g_cnt[NMAX];          // histogram counts, then scatter cursor
__device__ int   g_csr[EMAX];          // src indices bucketed by dst
__device__ int   g_bsum[128];
__device__ float g_buf [NMAX * HID];   // transformed features (X@W)
__device__ float g_hbuf[NMAX * HID];   // layer activations
__device__ float g_pM[GRED * NCLS];
__device__ float g_pS[GRED * NCLS];
__device__ float g_logZ[NCLS];
__device__ float g_loss[2];            // {sum picked, sum mask}

// ------------------------------- init -------------------------------
__global__ void k_init(int N) {
    int i = blockIdx.x * blockDim.x + threadIdx.x;
    if (i < N) g_cnt[i] = 0;
    if (i == 0) { g_loss[0] = 0.f; g_loss[1] = 0.f; }
}

// --------------------------- CSR build ------------------------------
__global__ void k_hist(const int* __restrict__ dst, int E) {
    for (int e = blockIdx.x * blockDim.x + threadIdx.x; e < E;
         e += gridDim.x * blockDim.x)
        atomicAdd(&g_cnt[dst[e]], 1);
}

__global__ void k_scanA(int N) {   // per-block exclusive scan of g_cnt
    __shared__ int sh[SCAN_B];
    int i = blockIdx.x * SCAN_B + threadIdx.x;
    int c = (i < N) ? g_cnt[i] : 0;
    sh[threadIdx.x] = c;
    __syncthreads();
    for (int off = 1; off < SCAN_B; off <<= 1) {
        int t = (threadIdx.x >= off) ? sh[threadIdx.x - off] : 0;
        __syncthreads();
        sh[threadIdx.x] += t;
        __syncthreads();
    }
    if (i < N) g_rowptr[i] = sh[threadIdx.x] - c;   // exclusive within block
    if (threadIdx.x == SCAN_B - 1) g_bsum[blockIdx.x] = sh[SCAN_B - 1];
}

__global__ void k_scanB(int NB, int N) {  // scan block sums (serial, tiny)
    if (threadIdx.x == 0) {
        int run = 0;
        for (int b = 0; b < NB; b++) { int t = g_bsum[b]; g_bsum[b] = run; run += t; }
        g_rowptr[N] = run;
    }
}

__global__ void k_scanC(int N) {   // add block offsets; init scatter cursor
    int i = blockIdx.x * SCAN_B + threadIdx.x;
    if (i < N) {
        int v = g_rowptr[i] + g_bsum[blockIdx.x];
        g_rowptr[i] = v;
        g_cnt[i] = v;
    }
}

__global__ void k_scatter(const int* __restrict__ src,
                          const int* __restrict__ dst, int E) {
    for (int e = blockIdx.x * blockDim.x + threadIdx.x; e < E;
         e += gridDim.x * blockDim.x) {
        int pos = atomicAdd(&g_cnt[dst[e]], 1);
        g_csr[pos] = src[e];
    }
}

// ------------------------------ GEMM --------------------------------
// Y[N,KOUT] = X[N,64] @ W[64,KOUT]   (64 rows per block, 4 threads/row)
template <int KOUT>
__global__ void k_gemm(const float* __restrict__ X, const float* __restrict__ W,
                       float* __restrict__ Y, int N) {
    constexpr int CPT = KOUT / 4;
    __shared__ float sX[64 * 65];        // padded to kill bank conflicts
    __shared__ float sW[64 * KOUT];
    int tid = threadIdx.x;
    int rbase = blockIdx.x * 64;

    const float4* X4 = (const float4*)(X + (size_t)rbase * 64);
    for (int t = tid; t < 1024; t += 256) {      // 64 rows x 16 float4
        int r = t >> 4, cc = (t & 15) * 4;
        float4 v = make_float4(0.f, 0.f, 0.f, 0.f);
        if (rbase + r < N) v = X4[t];
        sX[r * 65 + cc + 0] = v.x; sX[r * 65 + cc + 1] = v.y;
        sX[r * 65 + cc + 2] = v.z; sX[r * 65 + cc + 3] = v.w;
    }
    const float4* W4 = (const float4*)W;
    float4* sW4 = (float4*)sW;
    for (int t = tid; t < 64 * KOUT / 4; t += 256) sW4[t] = W4[t];
    __syncthreads();

    int r = tid >> 2, q = tid & 3;
    float acc[CPT];
#pragma unroll
    for (int c = 0; c < CPT; c++) acc[c] = 0.f;
#pragma unroll
    for (int k = 0; k < 64; k++) {
        float a = sX[r * 65 + k];
#pragma unroll
        for (int c = 0; c < CPT; c++)
            acc[c] = fmaf(a, sW[k * KOUT + q * CPT + c], acc[c]);
    }
    int row = rbase + r;
    if (row < N) {
#pragma unroll
        for (int c = 0; c < CPT; c++)
            Y[(size_t)row * KOUT + q * CPT + c] = acc[c];
    }
}

// ------------------------------ SpMM --------------------------------
// out[v,:] = act( sum_{e: dst==v} g[src[e],:] + bias )   64-wide, warp/node
__global__ void k_spmm64(const float* __restrict__ g,
                         const float* __restrict__ bias,
                         float* __restrict__ out, int N, int doRelu) {
    int w = (blockIdx.x * blockDim.x + threadIdx.x) >> 5;
    int lane = threadIdx.x & 31;
    if (w >= N) return;
    int beg = g_rowptr[w], end = g_rowptr[w + 1];
    float2 acc = make_float2(0.f, 0.f);
    const float2* gv = (const float2*)g;
    for (int i = beg; i < end; i += 32) {
        int n = end - i; if (n > 32) n = 32;
        int sidx = g_csr[i + (lane < n ? lane : 0)];
        int j = 0;
        for (; j + 4 <= n; j += 4) {
            int s0 = __shfl_sync(0xffffffffu, sidx, j + 0);
            int s1 = __shfl_sync(0xffffffffu, sidx, j + 1);
            int s2 = __shfl_sync(0xffffffffu, sidx, j + 2);
            int s3 = __shfl_sync(0xffffffffu, sidx, j + 3);
            float2 v0 = gv[(size_t)s0 * 32 + lane];
            float2 v1 = gv[(size_t)s1 * 32 + lane];
            float2 v2 = gv[(size_t)s2 * 32 + lane];
            float2 v3 = gv[(size_t)s3 * 32 + lane];
            acc.x += (v0.x + v1.x) + (v2.x + v3.x);
            acc.y += (v0.y + v1.y) + (v2.y + v3.y);
        }
        for (; j < n; j++) {
            int s = __shfl_sync(0xffffffffu, sidx, j);
            float2 v = gv[(size_t)s * 32 + lane];
            acc.x += v.x; acc.y += v.y;
        }
    }
    float2 b = ((const float2*)bias)[lane];
    acc.x += b.x; acc.y += b.y;
    if (doRelu) { acc.x = fmaxf(acc.x, 0.f); acc.y = fmaxf(acc.y, 0.f); }
    ((float2*)out)[(size_t)w * 32 + lane] = acc;
}

// 40-wide final aggregation: rep[v,:] = sum g2[src,:] + b2
__global__ void k_spmm40(const float* __restrict__ g,
                         const float* __restrict__ bias,
                         float* __restrict__ out, int N) {
    int w = (blockIdx.x * blockDim.x + threadIdx.x) >> 5;
    int lane = threadIdx.x & 31;
    if (w >= N) return;
    int beg = g_rowptr[w], end = g_rowptr[w + 1];
    float a0 = 0.f, a1 = 0.f;
    for (int i = beg; i < end; i += 32) {
        int n = end - i; if (n > 32) n = 32;
        int sidx = g_csr[i + (lane < n ? lane : 0)];
        for (int j = 0; j < n; j++) {
            int s = __shfl_sync(0xffffffffu, sidx, j);
            const float* row = g + (size_t)s * NCLS;
            a0 += row[lane < NCLS ? lane : 0] * (lane < NCLS ? 1.f : 0.f);
            if (lane < NCLS - 32) a1 += row[32 + lane];
        }
    }
    if (lane < NCLS) out[(size_t)w * NCLS + lane] = a0 + bias[lane];
    if (lane < NCLS - 32) out[(size_t)w * NCLS + 32 + lane] = a1 + bias[32 + lane];
}

// ---------------------- axis-0 log-softmax + loss -------------------
__device__ __forceinline__ void msmerge(float& M, float& S, float m2, float s2) {
    if (m2 > M) { S = S * __expf(M - m2) + s2; M = m2; }
    else if (m2 > -INFINITY) S += s2 * __expf(m2 - M);
}

__global__ void k_colreduce(const float* __restrict__ rep, int N) {
    // blockDim = 320 (8 row-groups x 40 cols): coalesced row reads
    int col = threadIdx.x % NCLS;
    int sub = threadIdx.x / NCLS;
    float m = -INFINITY, s = 0.f;
    for (int r = blockIdx.x * 8 + sub; r < N; r += 8 * gridDim.x) {
        float x = rep[(size_t)r * NCLS + col];
        if (x > m) { s = s * __expf(m - x) + 1.f; m = x; }
        else s += __expf(x - m);
    }
    __shared__ float shm[320], shs[320];
    shm[threadIdx.x] = m; shs[threadIdx.x] = s;
    __syncthreads();
    if (sub == 0) {
        float M = m, S = s;
        for (int k = 1; k < 8; k++) msmerge(M, S, shm[k * NCLS + col], shs[k * NCLS + col]);
        g_pM[blockIdx.x * NCLS + col] = M;
        g_pS[blockIdx.x * NCLS + col] = S;
    }
}

__global__ void k_colfinal() {
    int col = threadIdx.x;
    if (col >= NCLS) return;
    float M = -INFINITY, S = 0.f;
    for (int b = 0; b < GRED; b++) msmerge(M, S, g_pM[b * NCLS + col], g_pS[b * NCLS + col]);
    g_logZ[col] = M + logf(S);
}

__global__ void k_loss(const float* __restrict__ rep,
                       const int* __restrict__ labels,
                       const int* __restrict__ mask, int N) {
    float lp = 0.f, lm = 0.f;
    for (int n = blockIdx.x * blockDim.x + threadIdx.x; n < N;
         n += gridDim.x * blockDim.x) {
        if (mask[n] != 0) {
            int l = labels[n];
            lp += rep[(size_t)n * NCLS + l] - g_logZ[l];
            lm += 1.f;
        }
    }
    __shared__ float sp[256], sm[256];
    sp[threadIdx.x] = lp; sm[threadIdx.x] = lm;
    __syncthreads();
    for (int off = 128; off > 0; off >>= 1) {
        if (threadIdx.x < off) {
            sp[threadIdx.x] += sp[threadIdx.x + off];
            sm[threadIdx.x] += sm[threadIdx.x + off];
        }
        __syncthreads();
    }
    if (threadIdx.x == 0) {
        atomicAdd(&g_loss[0], sp[0]);
        atomicAdd(&g_loss[1], sm[0]);
    }
}

__global__ void k_lossfinal(float* __restrict__ out_loss) {
    *out_loss = -g_loss[0] / g_loss[1];
}

// ------------------------------ launch ------------------------------
extern "C" void kernel_launch(void* const* d_in, const int* in_sizes, int n_in,
                              void* d_out, int out_size) {
    const float* features = (const float*)d_in[0];
    const float* W0 = (const float*)d_in[1];
    const float* b0 = (const float*)d_in[2];
    const float* W1 = (const float*)d_in[3];
    const float* b1 = (const float*)d_in[4];
    const float* W2 = (const float*)d_in[5];
    const float* b2 = (const float*)d_in[6];
    const int*   src = (const int*)d_in[7];
    const int*   dst = (const int*)d_in[8];
    const int*   labels = (const int*)d_in[9];
    const int*   mask = (const int*)d_in[10];   // bool serialized as int32

    int N = in_sizes[0] / HID;
    int E = in_sizes[7];
    if (N > NMAX) N = NMAX;
    if (E > EMAX) E = EMAX;

    float* rep = (float*)d_out;   // [N, 40] written directly

    float* gbuf; cudaGetSymbolAddress((void**)&gbuf, g_buf);
    float* hbuf; cudaGetSymbolAddress((void**)&hbuf, g_hbuf);

    int NB = (N + SCAN_B - 1) / SCAN_B;

    // 1. CSR build (by dst)
    k_init<<<(N + 255) / 256, 256>>>(N);
    k_hist<<<2048, 256>>>(dst, E);
    k_scanA<<<NB, SCAN_B>>>(N);
    k_scanB<<<1, 32>>>(NB, N);
    k_scanC<<<NB, SCAN_B>>>(N);
    k_scatter<<<2048, 256>>>(src, dst, E);

    int gemmBlocks = (N + 63) / 64;
    int spmmBlocks = (N * 32 + 255) / 256;

    // 2. Layer 0: g = X@W0 ; h0 = relu(A@g + b0)
    k_gemm<64><<<gemmBlocks, 256>>>(features, W0, gbuf, N);
    k_spmm64<<<spmmBlocks, 256>>>(gbuf, b0, hbuf, N, 1);

    // 3. Layer 1
    k_gemm<64><<<gemmBlocks, 256>>>(hbuf, W1, gbuf, N);
    k_spmm64<<<spmmBlocks, 256>>>(gbuf, b1, hbuf, N, 1);

    // 4. Layer 2 (40-wide): g2 = h1@W2 ; rep = A@g2 + b2
    k_gemm<40><<<gemmBlocks, 256>>>(hbuf, W2, gbuf, N);
    k_spmm40<<<spmmBlocks, 256>>>(gbuf, b2, rep, N);

    // 5. axis-0 log-softmax + NLL loss
    k_colreduce<<<GRED, 320>>>(rep, N);
    k_colfinal<<<1, 64>>>();
    k_loss<<<256, 256>>>(rep, labels, mask, N);
    if (out_size > N * NCLS)
        k_lossfinal<<<1, 1>>>(rep + (size_t)N * NCLS);
}

// round 4
// speedup vs baseline: 1.0443x; 1.0443x over previous
#include <cuda_runtime.h>
#include <cuda_fp16.h>
#include <math.h>

#define NMAX 100000
#define EMAX 1700000
#define HID  64
#define NCLS 40
#define GRED 256
#define SCAN_B 1024

// -------- scratch (device globals: no allocations allowed) --------
__device__ int    g_rowptr[NMAX + 1];
__device__ int    g_cnt[NMAX];          // histogram counts, then scatter cursor
__device__ int    g_csr[EMAX];          // src indices bucketed by dst
__device__ int    g_bsum[128];
__device__ __half g_buf [NMAX * HID];   // transformed features (X@W), fp16, row stride 64
__device__ float  g_hbuf[NMAX * HID];   // layer activations, fp32
__device__ float  g_pM[GRED * NCLS];
__device__ float  g_pS[GRED * NCLS];
__device__ float  g_logZ[NCLS];
__device__ float  g_loss[2];

// ------------------------------- init -------------------------------
__global__ void k_init(int N) {
    int i = blockIdx.x * blockDim.x + threadIdx.x;
    if (i < N) g_cnt[i] = 0;
    if (i == 0) { g_loss[0] = 0.f; g_loss[1] = 0.f; }
}

// --------------------------- CSR build ------------------------------
__global__ void k_hist(const int* __restrict__ dst, int E) {
    for (int e = blockIdx.x * blockDim.x + threadIdx.x; e < E;
         e += gridDim.x * blockDim.x)
        atomicAdd(&g_cnt[dst[e]], 1);
}

__global__ void k_scanA(int N) {   // per-block scan of g_cnt
    __shared__ int sh[SCAN_B];
    int i = blockIdx.x * SCAN_B + threadIdx.x;
    int c = (i < N) ? g_cnt[i] : 0;
    sh[threadIdx.x] = c;
    __syncthreads();
    for (int off = 1; off < SCAN_B; off <<= 1) {
        int t = (threadIdx.x >= off) ? sh[threadIdx.x - off] : 0;
        __syncthreads();
        sh[threadIdx.x] += t;
        __syncthreads();
    }
    if (i < N) g_rowptr[i] = sh[threadIdx.x] - c;   // exclusive within block
    if (threadIdx.x == SCAN_B - 1) g_bsum[blockIdx.x] = sh[SCAN_B - 1];
}

__global__ void k_scanB(int NB, int N) {  // scan block sums (serial, tiny)
    if (threadIdx.x == 0) {
        int run = 0;
        for (int b = 0; b < NB; b++) { int t = g_bsum[b]; g_bsum[b] = run; run += t; }
        g_rowptr[N] = run;
    }
}

__global__ void k_scanC(int N) {   // add block offsets; init scatter cursor
    int i = blockIdx.x * SCAN_B + threadIdx.x;
    if (i < N) {
        int v = g_rowptr[i] + g_bsum[blockIdx.x];
        g_rowptr[i] = v;
        g_cnt[i] = v;
    }
}

__global__ void k_scatter(const int* __restrict__ src,
                          const int* __restrict__ dst, int E) {
    for (int e = blockIdx.x * blockDim.x + threadIdx.x; e < E;
         e += gridDim.x * blockDim.x) {
        int pos = atomicAdd(&g_cnt[dst[e]], 1);
        g_csr[pos] = src[e];
    }
}

// ------------------------------ GEMM --------------------------------
// Y[N, OSTRIDE(fp16)] = X[N,64] @ W[64,KOUT]   (64 rows/block, 4 thr/row)
template <int KOUT, int OSTRIDE>
__global__ void k_gemm_h(const float* __restrict__ X, const float* __restrict__ W,
                         __half* __restrict__ Y, int N) {
    constexpr int CPT = KOUT / 4;
    __shared__ float sX[64 * 65];
    __shared__ float sW[64 * KOUT];
    int tid = threadIdx.x;
    int rbase = blockIdx.x * 64;

    const float4* X4 = (const float4*)(X + (size_t)rbase * 64);
    for (int t = tid; t < 1024; t += 256) {
        int r = t >> 4, cc = (t & 15) * 4;
        float4 v = make_float4(0.f, 0.f, 0.f, 0.f);
        if (rbase + r < N) v = X4[t];
        sX[r * 65 + cc + 0] = v.x; sX[r * 65 + cc + 1] = v.y;
        sX[r * 65 + cc + 2] = v.z; sX[r * 65 + cc + 3] = v.w;
    }
    const float4* W4 = (const float4*)W;
    float4* sW4 = (float4*)sW;
    for (int t = tid; t < 64 * KOUT / 4; t += 256) sW4[t] = W4[t];
    __syncthreads();

    int r = tid >> 2, q = tid & 3;
    float acc[CPT];
#pragma unroll
    for (int c = 0; c < CPT; c++) acc[c] = 0.f;
#pragma unroll
    for (int k = 0; k < 64; k++) {
        float a = sX[r * 65 + k];
#pragma unroll
        for (int c = 0; c < CPT; c++)
            acc[c] = fmaf(a, sW[k * KOUT + q * CPT + c], acc[c]);
    }
    int row = rbase + r;
    if (row < N) {
        __half* yr = Y + (size_t)row * OSTRIDE + q * CPT;
#pragma unroll
        for (int c = 0; c < CPT; c += 2)
            *(__half2*)(yr + c) = __floats2half2_rn(acc[c], acc[c + 1]);
    }
}

// ------------------------------ SpMM --------------------------------
// out[v,:] = act( sum_{e: dst==v} g[src[e],:] + bias )   fp16 gather, fp32 acc
__global__ void k_spmm64h(const __half2* __restrict__ g,
                          const float* __restrict__ bias,
                          float* __restrict__ out, int N, int doRelu) {
    const unsigned FULL = 0xffffffffu;
    int w = (blockIdx.x * blockDim.x + threadIdx.x) >> 5;
    int lane = threadIdx.x & 31;
    if (w >= N) return;
    int beg = g_rowptr[w], end = g_rowptr[w + 1];
    float2 acc = make_float2(0.f, 0.f);
    for (int i = beg; i < end; i += 32) {
        int n = end - i; if (n > 32) n = 32;
        int sidx = g_csr[i + (lane < n ? lane : 0)];
        int j = 0;
        for (; j + 8 <= n; j += 8) {
            int s[8];
#pragma unroll
            for (int u = 0; u < 8; u++) s[u] = __shfl_sync(FULL, sidx, j + u);
            __half2 v[8];
#pragma unroll
            for (int u = 0; u < 8; u++) v[u] = g[(size_t)s[u] * 32 + lane];
#pragma unroll
            for (int u = 0; u < 8; u++) {
                float2 f = __half22float2(v[u]);
                acc.x += f.x; acc.y += f.y;
            }
        }
        for (; j < n; j++) {
            int s = __shfl_sync(FULL, sidx, j);
            float2 f = __half22float2(g[(size_t)s * 32 + lane]);
            acc.x += f.x; acc.y += f.y;
        }
    }
    float2 b = ((const float2*)bias)[lane];
    acc.x += b.x; acc.y += b.y;
    if (doRelu) { acc.x = fmaxf(acc.x, 0.f); acc.y = fmaxf(acc.y, 0.f); }
    ((float2*)out)[(size_t)w * 32 + lane] = acc;
}

// 40-wide final aggregation from fp16 rows padded to stride 64
__global__ void k_spmm40h(const __half2* __restrict__ g,
                          const float* __restrict__ bias,
                          float* __restrict__ out, int N) {
    const unsigned FULL = 0xffffffffu;
    int w = (blockIdx.x * blockDim.x + threadIdx.x) >> 5;
    int lane = threadIdx.x & 31;
    if (w >= N) return;
    int beg = g_rowptr[w], end = g_rowptr[w + 1];
    float2 acc = make_float2(0.f, 0.f);
    bool act = (lane < NCLS / 2);   // 20 lanes carry the 40 cols
    for (int i = beg; i < end; i += 32) {
        int n = end - i; if (n > 32) n = 32;
        int sidx = g_csr[i + (lane < n ? lane : 0)];
        int j = 0;
        for (; j + 8 <= n; j += 8) {
            int s[8];
#pragma unroll
            for (int u = 0; u < 8; u++) s[u] = __shfl_sync(FULL, sidx, j + u);
            if (act) {
                __half2 v[8];
#pragma unroll
                for (int u = 0; u < 8; u++) v[u] = g[(size_t)s[u] * 32 + lane];
#pragma unroll
                for (int u = 0; u < 8; u++) {
                    float2 f = __half22float2(v[u]);
                    acc.x += f.x; acc.y += f.y;
                }
            }
        }
        for (; j < n; j++) {
            int s = __shfl_sync(FULL, sidx, j);
            if (act) {
                float2 f = __half22float2(g[(size_t)s * 32 + lane]);
                acc.x += f.x; acc.y += f.y;
            }
        }
    }
    if (act) {
        float2 b = ((const float2*)bias)[lane];
        acc.x += b.x; acc.y += b.y;
        ((float2*)(out + (size_t)w * NCLS))[lane] = acc;
    }
}

// ---------------------- axis-0 log-softmax + loss -------------------
__device__ __forceinline__ void msmerge(float& M, float& S, float m2, float s2) {
    if (m2 > M) { S = S * __expf(M - m2) + s2; M = m2; }
    else if (m2 > -INFINITY) S += s2 * __expf(m2 - M);
}

__global__ void k_colreduce(const float* __restrict__ rep, int N) {
    int col = threadIdx.x % NCLS;
    int sub = threadIdx.x / NCLS;
    float m = -INFINITY, s = 0.f;
    for (int r = blockIdx.x * 8 + sub; r < N; r += 8 * gridDim.x) {
        float x = rep[(size_t)r * NCLS + col];
        if (x > m) { s = s * __expf(m - x) + 1.f; m = x; }
        else s += __expf(x - m);
    }
    __shared__ float shm[320], shs[320];
    shm[threadIdx.x] = m; shs[threadIdx.x] = s;
    __syncthreads();
    if (sub == 0) {
        float M = m, S = s;
        for (int k = 1; k < 8; k++) msmerge(M, S, shm[k * NCLS + col], shs[k * NCLS + col]);
        g_pM[blockIdx.x * NCLS + col] = M;
        g_pS[blockIdx.x * NCLS + col] = S;
    }
}

__global__ void k_colfinal() {
    int col = threadIdx.x;
    if (col >= NCLS) return;
    float M = -INFINITY, S = 0.f;
    for (int b = 0; b < GRED; b++) msmerge(M, S, g_pM[b * NCLS + col], g_pS[b * NCLS + col]);
    g_logZ[col] = M + logf(S);
}

__global__ void k_loss(const float* __restrict__ rep,
                       const int* __restrict__ labels,
                       const int* __restrict__ mask, int N) {
    float lp = 0.f, lm = 0.f;
    for (int n = blockIdx.x * blockDim.x + threadIdx.x; n < N;
         n += gridDim.x * blockDim.x) {
        if (mask[n] != 0) {
            int l = labels[n];
            lp += rep[(size_t)n * NCLS + l] - g_logZ[l];
            lm += 1.f;
        }
    }
    __shared__ float sp[256], sm[256];
    sp[threadIdx.x] = lp; sm[threadIdx.x] = lm;
    __syncthreads();
    for (int off = 128; off > 0; off >>= 1) {
        if (threadIdx.x < off) {
            sp[threadIdx.x] += sp[threadIdx.x + off];
            sm[threadIdx.x] += sm[threadIdx.x + off];
        }
        __syncthreads();
    }
    if (threadIdx.x == 0) {
        atomicAdd(&g_loss[0], sp[0]);
        atomicAdd(&g_loss[1], sm[0]);
    }
}

__global__ void k_lossfinal(float* __restrict__ out_loss) {
    *out_loss = -g_loss[0] / g_loss[1];
}

// ------------------------------ launch ------------------------------
extern "C" void kernel_launch(void* const* d_in, const int* in_sizes, int n_in,
                              void* d_out, int out_size) {
    const float* features = (const float*)d_in[0];
    const float* W0 = (const float*)d_in[1];
    const float* b0 = (const float*)d_in[2];
    const float* W1 = (const float*)d_in[3];
    const float* b1 = (const float*)d_in[4];
    const float* W2 = (const float*)d_in[5];
    const float* b2 = (const float*)d_in[6];
    const int*   src = (const int*)d_in[7];
    const int*   dst = (const int*)d_in[8];
    const int*   labels = (const int*)d_in[9];
    const int*   mask = (const int*)d_in[10];   // bool serialized as int32

    int N = in_sizes[0] / HID;
    int E = in_sizes[7];
    if (N > NMAX) N = NMAX;
    if (E > EMAX) E = EMAX;

    float* rep = (float*)d_out;

    __half* gbuf; cudaGetSymbolAddress((void**)&gbuf, g_buf);
    float*  hbuf; cudaGetSymbolAddress((void**)&hbuf, g_hbuf);

    int NB = (N + SCAN_B - 1) / SCAN_B;
    int gemmBlocks = (N + 63) / 64;
    int spmmBlocks = (N * 32 + 255) / 256;

    // CSR build
    k_init<<<(N + 255) / 256, 256>>>(N);
    k_hist<<<2048, 256>>>(dst, E);
    k_scanA<<<NB, SCAN_B>>>(N);
    k_scanB<<<1, 32>>>(NB, N);
    k_scanC<<<NB, SCAN_B>>>(N);
    k_scatter<<<2048, 256>>>(src, dst, E);

    // Layer 0
    k_gemm_h<64, 64><<<gemmBlocks, 256>>>(features, W0, gbuf, N);
    k_spmm64h<<<spmmBlocks, 256>>>((const __half2*)gbuf, b0, hbuf, N, 1);
    // Layer 1
    k_gemm_h<64, 64><<<gemmBlocks, 256>>>(hbuf, W1, gbuf, N);
    k_spmm64h<<<spmmBlocks, 256>>>((const __half2*)gbuf, b1, hbuf, N, 1);
    // Layer 2 (40-wide, padded to stride 64)
    k_gemm_h<40, 64><<<gemmBlocks, 256>>>(hbuf, W2, gbuf, N);
    k_spmm40h<<<spmmBlocks, 256>>>((const __half2*)gbuf, b2, rep, N);

    // axis-0 log-softmax + NLL loss
    k_colreduce<<<GRED, 320>>>(rep, N);
    k_colfinal<<<1, 64>>>();
    k_loss<<<256, 256>>>(rep, labels, mask, N);
    if (out_size > N * NCLS)
        k_lossfinal<<<1, 1>>>(rep + (size_t)N * NCLS);
}

// round 5
// speedup vs baseline: 1.5422x; 1.4768x over previous
#include <cuda_runtime.h>
#include <cuda_fp16.h>
#include <math.h>

#define NMAX 100000
#define EMAX 1700000
#define HID  64
#define NCLS 40
#define GRED 256
#define SCAN_B 1024

// -------- scratch (device globals: no allocations allowed) --------
__device__ int    g_rowptr[NMAX + 1];
__device__ int    g_cnt[NMAX];          // histogram counts, then scatter cursor
__device__ int    g_csr[EMAX];          // src indices bucketed by dst
__device__ int    g_bsum[128];
__device__ int    g_ctr;                // k_loss completion counter
__device__ __half g_buf [NMAX * HID];   // transformed features (X@W), fp16, stride 64
__device__ float  g_hbuf[NMAX * HID];   // layer activations, fp32
__device__ float  g_pM[GRED * NCLS];
__device__ float  g_pS[GRED * NCLS];
__device__ float  g_logZ[NCLS];
__device__ float  g_loss[2];

// ---------------------- fast exp (FMA pipe, x <= 0) ------------------
__device__ __forceinline__ float fexp(float x) {
    x = fmaxf(x, -80.0f);
    float y = x * 1.44269504f;          // x * log2(e)
    int   ni = __float2int_rn(y);
    float f = y - (float)ni;            // [-0.5, 0.5]
    float g = f * 0.69314718f;          // back to natural
    float p = fmaf(g, 1.3888889e-3f, 8.3333333e-3f);
    p = fmaf(p, g, 4.1666667e-2f);
    p = fmaf(p, g, 1.6666667e-1f);
    p = fmaf(p, g, 0.5f);
    p = fmaf(p, g, 1.0f);
    p = fmaf(p, g, 1.0f);
    return p * __int_as_float((ni + 127) << 23);
}

// ------------------------------- init -------------------------------
__global__ void k_init(int N) {
    int i = blockIdx.x * blockDim.x + threadIdx.x;
    if (i < N) g_cnt[i] = 0;
    if (i == 0) { g_loss[0] = 0.f; g_loss[1] = 0.f; g_ctr = 0; }
}

// --------------------------- CSR build ------------------------------
__global__ void k_hist(const int* __restrict__ dst, int E) {
    for (int e = blockIdx.x * blockDim.x + threadIdx.x; e < E;
         e += gridDim.x * blockDim.x)
        atomicAdd(&g_cnt[dst[e]], 1);
}

__global__ void k_scanA(int N) {
    __shared__ int sh[SCAN_B];
    int i = blockIdx.x * SCAN_B + threadIdx.x;
    int c = (i < N) ? g_cnt[i] : 0;
    sh[threadIdx.x] = c;
    __syncthreads();
    for (int off = 1; off < SCAN_B; off <<= 1) {
        int t = (threadIdx.x >= off) ? sh[threadIdx.x - off] : 0;
        __syncthreads();
        sh[threadIdx.x] += t;
        __syncthreads();
    }
    if (i < N) g_rowptr[i] = sh[threadIdx.x] - c;
    if (threadIdx.x == SCAN_B - 1) g_bsum[blockIdx.x] = sh[SCAN_B - 1];
}

__global__ void k_scanB(int NB, int N) {
    if (threadIdx.x == 0) {
        int run = 0;
        for (int b = 0; b < NB; b++) { int t = g_bsum[b]; g_bsum[b] = run; run += t; }
        g_rowptr[N] = run;
    }
}

__global__ void k_scanC(int N) {
    int i = blockIdx.x * SCAN_B + threadIdx.x;
    if (i < N) {
        int v = g_rowptr[i] + g_bsum[blockIdx.x];
        g_rowptr[i] = v;
        g_cnt[i] = v;
    }
}

__global__ void k_scatter(const int* __restrict__ src,
                          const int* __restrict__ dst, int E) {
    for (int e = blockIdx.x * blockDim.x + threadIdx.x; e < E;
         e += gridDim.x * blockDim.x) {
        int pos = atomicAdd(&g_cnt[dst[e]], 1);
        g_csr[pos] = src[e];
    }
}

// --------------------- register-tiled GEMM -------------------------
// Y[N, 64(fp16 stride)] = X[N,64] @ W[64,KOUT].
// 128 rows/block, 128 threads, thread tile 8 rows x CPN cols.
template <int KOUT>
__global__ void k_gemm_rt(const float* __restrict__ X, const float* __restrict__ W,
                          __half* __restrict__ Y, int N) {
    constexpr int CPN = KOUT / 8;     // 8 (KOUT=64) or 5 (KOUT=40)
    constexpr int SXS = 68;           // sX row stride (floats)
    extern __shared__ float smem[];
    float* sX = smem;                 // [128][68]
    float* sW = smem + 128 * SXS;     // [64][KOUT]
    int tid = threadIdx.x;
    int rbase = blockIdx.x * 128;

    // load X coalesced: 128 rows x 16 float4
    const float4* X4 = (const float4*)X;
    for (int i = tid; i < 2048; i += 128) {
        int row = i >> 4, k4 = i & 15;
        float4 v = make_float4(0.f, 0.f, 0.f, 0.f);
        if (rbase + row < N) v = X4[(size_t)(rbase + row) * 16 + k4];
        float* p = sX + row * SXS + k4 * 4;
        p[0] = v.x; p[1] = v.y; p[2] = v.z; p[3] = v.w;
    }
    for (int i = tid; i < 64 * KOUT / 4; i += 128)
        ((float4*)sW)[i] = ((const float4*)W)[i];
    __syncthreads();

    int ty = tid >> 3, tx = tid & 7;      // 16 row-groups x 8 col-groups
    const float* ap = sX + (ty * 8) * SXS;
    const float* wp = sW + tx * CPN;

    float acc[8][CPN];
#pragma unroll
    for (int i = 0; i < 8; i++)
#pragma unroll
        for (int j = 0; j < CPN; j++) acc[i][j] = 0.f;

#pragma unroll 4
    for (int kk = 0; kk < 32; kk++) {     // process k pairs
        int k = kk * 2;
        float2 a[8];
#pragma unroll
        for (int i = 0; i < 8; i++)
            a[i] = *(const float2*)(ap + i * SXS + k);
        float w0[CPN], w1[CPN];
#pragma unroll
        for (int j = 0; j < CPN; j++) {
            w0[j] = wp[(size_t)k * KOUT + j];
            w1[j] = wp[(size_t)(k + 1) * KOUT + j];
        }
#pragma unroll
        for (int i = 0; i < 8; i++)
#pragma unroll
            for (int j = 0; j < CPN; j++) {
                acc[i][j] = fmaf(a[i].x, w0[j], acc[i][j]);
                acc[i][j] = fmaf(a[i].y, w1[j], acc[i][j]);
            }
    }

    // store fp16, row stride 64
#pragma unroll
    for (int i = 0; i < 8; i++) {
        int row = rbase + ty * 8 + i;
        if (row >= N) break;
        __half* yr = Y + (size_t)row * 64 + tx * CPN;
        if (KOUT == 64) {
            union { uint4 u; __half2 h[4]; } pk;
#pragma unroll
            for (int j = 0; j < 4; j++)
                pk.h[j] = __floats2half2_rn(acc[i][2 * j], acc[i][2 * j + 1]);
            *(uint4*)yr = pk.u;
        } else {
#pragma unroll
            for (int j = 0; j < CPN; j++) yr[j] = __float2half_rn(acc[i][j]);
        }
    }
}

// ------------------------------ SpMM --------------------------------
__global__ void k_spmm64h(const __half2* __restrict__ g,
                          const float* __restrict__ bias,
                          float* __restrict__ out, int N, int doRelu) {
    const unsigned FULL = 0xffffffffu;
    int w = (blockIdx.x * blockDim.x + threadIdx.x) >> 5;
    int lane = threadIdx.x & 31;
    if (w >= N) return;
    int beg = g_rowptr[w], end = g_rowptr[w + 1];
    float2 acc = make_float2(0.f, 0.f);
    for (int i = beg; i < end; i += 32) {
        int n = end - i; if (n > 32) n = 32;
        int sidx = g_csr[i + (lane < n ? lane : 0)];
        int j = 0;
        for (; j + 8 <= n; j += 8) {
            int s[8];
#pragma unroll
            for (int u = 0; u < 8; u++) s[u] = __shfl_sync(FULL, sidx, j + u);
            __half2 v[8];
#pragma unroll
            for (int u = 0; u < 8; u++) v[u] = g[(size_t)s[u] * 32 + lane];
#pragma unroll
            for (int u = 0; u < 8; u++) {
                float2 f = __half22float2(v[u]);
                acc.x += f.x; acc.y += f.y;
            }
        }
        for (; j < n; j++) {
            int s = __shfl_sync(FULL, sidx, j);
            float2 f = __half22float2(g[(size_t)s * 32 + lane]);
            acc.x += f.x; acc.y += f.y;
        }
    }
    float2 b = ((const float2*)bias)[lane];
    acc.x += b.x; acc.y += b.y;
    if (doRelu) { acc.x = fmaxf(acc.x, 0.f); acc.y = fmaxf(acc.y, 0.f); }
    ((float2*)out)[(size_t)w * 32 + lane] = acc;
}

__global__ void k_spmm40h(const __half2* __restrict__ g,
                          const float* __restrict__ bias,
                          float* __restrict__ out, int N) {
    const unsigned FULL = 0xffffffffu;
    int w = (blockIdx.x * blockDim.x + threadIdx.x) >> 5;
    int lane = threadIdx.x & 31;
    if (w >= N) return;
    int beg = g_rowptr[w], end = g_rowptr[w + 1];
    float2 acc = make_float2(0.f, 0.f);
    bool act = (lane < NCLS / 2);
    for (int i = beg; i < end; i += 32) {
        int n = end - i; if (n > 32) n = 32;
        int sidx = g_csr[i + (lane < n ? lane : 0)];
        int j = 0;
        for (; j + 8 <= n; j += 8) {
            int s[8];
#pragma unroll
            for (int u = 0; u < 8; u++) s[u] = __shfl_sync(FULL, sidx, j + u);
            if (act) {
                __half2 v[8];
#pragma unroll
                for (int u = 0; u < 8; u++) v[u] = g[(size_t)s[u] * 32 + lane];
#pragma unroll
                for (int u = 0; u < 8; u++) {
                    float2 f = __half22float2(v[u]);
                    acc.x += f.x; acc.y += f.y;
                }
            }
        }
        for (; j < n; j++) {
            int s = __shfl_sync(FULL, sidx, j);
            if (act) {
                float2 f = __half22float2(g[(size_t)s * 32 + lane]);
                acc.x += f.x; acc.y += f.y;
            }
        }
    }
    if (act) {
        float2 b = ((const float2*)bias)[lane];
        acc.x += b.x; acc.y += b.y;
        ((float2*)(out + (size_t)w * NCLS))[lane] = acc;
    }
}

// ---------------------- axis-0 log-softmax + loss -------------------
__device__ __forceinline__ void msmerge(float& M, float& S, float m2, float s2) {
    if (m2 > M) { S = S * fexp(M - m2) + s2; M = m2; }
    else if (m2 > -INFINITY) S += s2 * fexp(m2 - M);
}

__global__ void k_colreduce(const float* __restrict__ rep, int N) {
    int col = threadIdx.x % NCLS;
    int sub = threadIdx.x / NCLS;
    float m = -INFINITY, s = 0.f;
    for (int r = blockIdx.x * 8 + sub; r < N; r += 8 * gridDim.x) {
        float x = rep[(size_t)r * NCLS + col];
        if (x > m) { s = s * fexp(m - x) + 1.f; m = x; }
        else s += fexp(x - m);
    }
    __shared__ float shm[320], shs[320];
    shm[threadIdx.x] = m; shs[threadIdx.x] = s;
    __syncthreads();
    if (sub == 0) {
        float M = m, S = s;
        for (int k = 1; k < 8; k++) msmerge(M, S, shm[k * NCLS + col], shs[k * NCLS + col]);
        g_pM[blockIdx.x * NCLS + col] = M;
        g_pS[blockIdx.x * NCLS + col] = S;
    }
}

__global__ void k_colfinal() {
    int col = threadIdx.x;
    if (col >= NCLS) return;
    float M = -INFINITY, S = 0.f;
    for (int b = 0; b < GRED; b++) msmerge(M, S, g_pM[b * NCLS + col], g_pS[b * NCLS + col]);
    g_logZ[col] = M + logf(S);
}

// fused loss reduction + finalization (arrival counter)
__global__ void k_loss(const float* __restrict__ rep,
                       const int* __restrict__ labels,
                       const int* __restrict__ mask, int N,
                       float* __restrict__ out_loss) {
    float lp = 0.f, lm = 0.f;
    for (int n = blockIdx.x * blockDim.x + threadIdx.x; n < N;
         n += gridDim.x * blockDim.x) {
        if (mask[n] != 0) {
            int l = labels[n];
            lp += rep[(size_t)n * NCLS + l] - g_logZ[l];
            lm += 1.f;
        }
    }
    __shared__ float sp[256], sm[256];
    sp[threadIdx.x] = lp; sm[threadIdx.x] = lm;
    __syncthreads();
    for (int off = 128; off > 0; off >>= 1) {
        if (threadIdx.x < off) {
            sp[threadIdx.x] += sp[threadIdx.x + off];
            sm[threadIdx.x] += sm[threadIdx.x + off];
        }
        __syncthreads();
    }
    if (threadIdx.x == 0) {
        atomicAdd(&g_loss[0], sp[0]);
        atomicAdd(&g_loss[1], sm[0]);
        __threadfence();
        int done = atomicAdd(&g_ctr, 1);
        if (done == gridDim.x - 1 && out_loss)
            *out_loss = -g_loss[0] / g_loss[1];
    }
}

// ------------------------------ launch ------------------------------
extern "C" void kernel_launch(void* const* d_in, const int* in_sizes, int n_in,
                              void* d_out, int out_size) {
    const float* features = (const float*)d_in[0];
    const float* W0 = (const float*)d_in[1];
    const float* b0 = (const float*)d_in[2];
    const float* W1 = (const float*)d_in[3];
    const float* b1 = (const float*)d_in[4];
    const float* W2 = (const float*)d_in[5];
    const float* b2 = (const float*)d_in[6];
    const int*   src = (const int*)d_in[7];
    const int*   dst = (const int*)d_in[8];
    const int*   labels = (const int*)d_in[9];
    const int*   mask = (const int*)d_in[10];

    int N = in_sizes[0] / HID;
    int E = in_sizes[7];
    if (N > NMAX) N = NMAX;
    if (E > EMAX) E = EMAX;

    float* rep = (float*)d_out;
    float* lossptr = (out_size > N * NCLS) ? rep + (size_t)N * NCLS : nullptr;

    __half* gbuf; cudaGetSymbolAddress((void**)&gbuf, g_buf);
    float*  hbuf; cudaGetSymbolAddress((void**)&hbuf, g_hbuf);

    const int SM64 = (128 * 68 + 64 * 64) * 4;
    const int SM40 = (128 * 68 + 64 * 40) * 4;
    cudaFuncSetAttribute(k_gemm_rt<64>, cudaFuncAttributeMaxDynamicSharedMemorySize, SM64);
    cudaFuncSetAttribute(k_gemm_rt<40>, cudaFuncAttributeMaxDynamicSharedMemorySize, SM40);

    int NB = (N + SCAN_B - 1) / SCAN_B;
    int gemmBlocks = (N + 127) / 128;
    int spmmBlocks = (N * 32 + 255) / 256;

    // CSR build; gemm0 hoisted to launch slot 4 (profiling telemetry)
    k_init<<<(N + 255) / 256, 256>>>(N);
    k_hist<<<2048, 256>>>(dst, E);
    k_scanA<<<NB, SCAN_B>>>(N);
    k_gemm_rt<64><<<gemmBlocks, 128, SM64>>>(features, W0, gbuf, N);
    k_scanB<<<1, 32>>>(NB, N);
    k_scanC<<<NB, SCAN_B>>>(N);
    k_scatter<<<2048, 256>>>(src, dst, E);

    // Layer 0 aggregate
    k_spmm64h<<<spmmBlocks, 256>>>((const __half2*)gbuf, b0, hbuf, N, 1);
    // Layer 1
    k_gemm_rt<64><<<gemmBlocks, 128, SM64>>>(hbuf, W1, gbuf, N);
    k_spmm64h<<<spmmBlocks, 256>>>((const __half2*)gbuf, b1, hbuf, N, 1);
    // Layer 2 (40-wide)
    k_gemm_rt<40><<<gemmBlocks, 128, SM40>>>(hbuf, W2, gbuf, N);
    k_spmm40h<<<spmmBlocks, 256>>>((const __half2*)gbuf, b2, rep, N);

    // axis-0 log-softmax + NLL loss
    k_colreduce<<<GRED, 320>>>(rep, N);
    k_colfinal<<<1, 64>>>();
    k_loss<<<256, 256>>>(rep, labels, mask, N, lossptr);
}